// round 7
// baseline (speedup 1.0000x reference)
#include <cuda_runtime.h>
#include <cstdint>

// Problem constants
#define B_   4
#define S_   2048
#define D_   768
#define NH_  4
#define DH_  192
#define KC_  4
#define EPS_ 1e-5f

// Scratch (device globals; no allocation allowed)
__device__ float g_xconv[B_ * S_ * D_];            // 25 MB
__device__ float g_G[4 * B_ * S_ * D_];            // 100 MB: [(b*NH+h)*S+s]*768 + g*192 + e
__device__ float g_yraw[B_ * S_ * D_];             // 25 MB: raw h outputs (B,S,D)

// ---------------------------------------------------------------------------
// Kernel 1: causal depthwise conv1d + swish
// ---------------------------------------------------------------------------
__global__ __launch_bounds__(256) void conv_swish_kernel(
    const float* __restrict__ x, const float* __restrict__ ck,
    const float* __restrict__ cb)
{
    int idx = blockIdx.x * 256 + threadIdx.x;
    if (idx >= B_ * S_ * D_) return;
    int d = idx % D_;
    int s = (idx / D_) & (S_ - 1);
    float acc = cb[d];
    const float* xp = x + idx;
#pragma unroll
    for (int j = 0; j < KC_; j++) {
        int ss = s - (KC_ - 1) + j;
        if (ss >= 0) acc += ck[j * D_ + d] * xp[(j - (KC_ - 1)) * D_];
    }
    g_xconv[idx] = acc / (1.f + __expf(-acc));
}

// ---------------------------------------------------------------------------
// Kernel 2: headwise gate GEMMs (R3 version — known good).
// ---------------------------------------------------------------------------
__global__ __launch_bounds__(256) void gate_gemm_kernel(
    const float* __restrict__ x,
    const float* __restrict__ Wi, const float* __restrict__ Wf,
    const float* __restrict__ Wz, const float* __restrict__ Wo)
{
    const int gz = blockIdx.z;
    const int g = gz >> 2;
    const int h = gz & 3;
    const float* A = (g < 2) ? g_xconv : x;
    const float* W = (g == 0) ? Wi : (g == 1) ? Wf : (g == 2) ? Wz : Wo;
    W += (size_t)h * DH_ * DH_;

    const int n0 = blockIdx.x * 64;
    const int m0 = blockIdx.y * 64;

    __shared__ __align__(16) float As[16][68];  // [k][m]
    __shared__ __align__(16) float Bs[16][68];  // [k][e]

    const int tid = threadIdx.x;
    const int tn = tid & 15;
    const int tm = tid >> 4;

    float acc[4][4] = {};

    for (int k0 = 0; k0 < DH_; k0 += 16) {
#pragma unroll
        for (int i = 0; i < 4; i++) {
            int lin = tid + i * 256;
            int r = lin >> 4, cc = lin & 15;
            As[cc][r] = A[(size_t)(m0 + r) * D_ + h * DH_ + k0 + cc];
        }
#pragma unroll
        for (int i = 0; i < 4; i++) {
            int lin = tid + i * 256;
            int r = lin >> 6, cc = lin & 63;
            Bs[r][cc] = W[(size_t)(k0 + r) * DH_ + n0 + cc];
        }
        __syncthreads();
#pragma unroll
        for (int kk = 0; kk < 16; kk++) {
            float4 av = *(const float4*)&As[kk][tm * 4];
            float4 bv = *(const float4*)&Bs[kk][tn * 4];
            acc[0][0] += av.x * bv.x; acc[0][1] += av.x * bv.y;
            acc[0][2] += av.x * bv.z; acc[0][3] += av.x * bv.w;
            acc[1][0] += av.y * bv.x; acc[1][1] += av.y * bv.y;
            acc[1][2] += av.y * bv.z; acc[1][3] += av.y * bv.w;
            acc[2][0] += av.z * bv.x; acc[2][1] += av.z * bv.y;
            acc[2][2] += av.z * bv.z; acc[2][3] += av.z * bv.w;
            acc[3][0] += av.w * bv.x; acc[3][1] += av.w * bv.y;
            acc[3][2] += av.w * bv.z; acc[3][3] += av.w * bv.w;
        }
        __syncthreads();
    }

#pragma unroll
    for (int i = 0; i < 4; i++) {
        int mm = m0 + tm * 4 + i;
        int bb = mm >> 11;
        int ss = mm & (S_ - 1);
        float4 v = make_float4(acc[i][0], acc[i][1], acc[i][2], acc[i][3]);
        *(float4*)&g_G[((size_t)(bb * NH_ + h) * S_ + ss) * D_ + g * DH_ + n0 + tn * 4] = v;
    }
}

// ---------------------------------------------------------------------------
// Kernel 3: sequential sLSTM scan (R3 structure + lightweight mbarrier sync
// + parallel transcendentals).
// One cluster of 4 CTAs per (b,h) chain; CTA rank q owns e in [48q, 48q+48).
// 192 threads: thread t handles gate g=t/48, local column el=t%48.
// R slice in registers as 96 f32x2 pairs.
// Per-step sync: one mbarrier per CTA, init count=4. Gate threads store h via
// st.shared::cluster; after bar.sync, threads 0-3 release-arrive on rank tid's
// barrier (exactly 4 arrivals per barrier per step). Acquire try_wait on
// parity at the top of the next step. No cluster.sync in the loop -> no
// per-step L1D flush, ~60-90cyc wakeup instead of ~490cyc.
// ---------------------------------------------------------------------------
__device__ __forceinline__ uint32_t smem_u32(const void* p) {
    uint32_t a;
    asm("{ .reg .u64 t; cvta.to.shared.u64 t, %1; cvt.u32.u64 %0, t; }"
        : "=r"(a) : "l"(p));
    return a;
}

#define CLUSTER_SYNC_() do { \
    asm volatile("barrier.cluster.arrive.aligned;" ::: "memory"); \
    asm volatile("barrier.cluster.wait.aligned;"   ::: "memory"); \
} while (0)

__device__ __forceinline__ void mbar_wait_acq(uint32_t addr, uint32_t parity) {
    uint32_t done;
    asm volatile("{\n\t.reg .pred p;\n\t"
        "mbarrier.try_wait.parity.acquire.cluster.shared::cta.b64 p, [%1], %2;\n\t"
        "selp.b32 %0, 1, 0, p;\n\t}"
        : "=r"(done) : "r"(addr), "r"(parity) : "memory");
    if (!done) {
        asm volatile("{\n\t.reg .pred P1;\n\t"
            "WL_%=:\n\t"
            "mbarrier.try_wait.parity.acquire.cluster.shared::cta.b64 P1, [%0], %1, 0x989680;\n\t"
            "@P1 bra.uni WD_%=;\n\t"
            "bra.uni WL_%=;\n\t"
            "WD_%=:\n\t}"
            :: "r"(addr), "r"(parity) : "memory");
    }
}

__global__ void __cluster_dims__(4, 1, 1) __launch_bounds__(192, 1)
slstm_scan_kernel(const float* __restrict__ R, const float* __restrict__ cell_bias)
{
    __shared__ __align__(16) float hbuf[2][DH_];
    __shared__ float spre[4 * 48];     // i, f, tanh(z), sigmoid(o)
    __shared__ __align__(8) unsigned long long mbar;

    const int tid   = threadIdx.x;
    const int chain = blockIdx.x >> 2;      // 0..15
    const int q     = blockIdx.x & 3;       // cluster rank
    const int b     = chain >> 2;
    const int h     = chain & 3;
    const int g     = tid / 48;
    const int el    = tid % 48;
    const int e     = q * 48 + el;

    // Load this thread's R column as 96 packed f32x2 pairs (over d).
    unsigned long long r2[96];
    {
        const float* Rcol = R + ((size_t)(g * NH_ + h)) * DH_ * DH_ + e;
#pragma unroll
        for (int j = 0; j < 96; j++) {
            float lo = Rcol[(2 * j) * DH_];
            float hi = Rcol[(2 * j + 1) * DH_];
            asm("mov.b64 %0, {%1, %2};" : "=l"(r2[j]) : "f"(lo), "f"(hi));
        }
    }
    const float cbias = cell_bias[g * D_ + h * DH_ + e];

    const float* Gp = g_G + ((size_t)(b * NH_ + h)) * S_ * D_ + g * DH_ + e;
    float* Yp = g_yraw + (size_t)b * S_ * D_ + h * DH_ + e;

    const uint32_t hb_base = smem_u32(&hbuf[0][0]);
    const uint32_t mb_addr = smem_u32(&mbar);

    hbuf[0][tid] = 0.f;
    hbuf[1][tid] = 0.f;
    if (tid == 0) {
        asm volatile("mbarrier.init.shared.b64 [%0], %1;"
                     :: "r"(mb_addr), "r"(4) : "memory");
    }
    __syncthreads();
    CLUSTER_SYNC_();   // hbuf + mbarrier init visible cluster-wide (once)

    // Remote hbuf and mbarrier addresses for all 4 ranks.
    uint32_t rhb[4], rmb[4];
#pragma unroll
    for (int rk = 0; rk < 4; rk++) {
        asm("mapa.shared::cluster.u32 %0, %1, %2;" : "=r"(rhb[rk]) : "r"(hb_base), "r"(rk));
        asm("mapa.shared::cluster.u32 %0, %1, %2;" : "=r"(rmb[rk]) : "r"(mb_addr), "r"(rk));
    }

    float c = 0.f, n = 0.f, m = 0.f;

    // 2-deep G prefetch ring.
    float gbuf0 = Gp[0];
    float gbuf1 = Gp[D_];

    for (int t = 0; t < S_; ++t) {
        float gnn = (t + 2 < S_) ? Gp[(size_t)(t + 2) * D_] : 0.f;

        // Wait for all 4 ranks' h(t) stores (paired with arrives at end of t-1).
        if (t > 0) mbar_wait_acq(mb_addr, (uint32_t)((t - 1) & 1));

        // Recurrent matvec: rec[e] = sum_d h[d] * R[g][h][d][e]
        const ulonglong2* h128 = (const ulonglong2*)hbuf[t & 1];
        unsigned long long a[4] = {0ull, 0ull, 0ull, 0ull};
#pragma unroll
        for (int jj = 0; jj < 48; jj++) {
            ulonglong2 hv = h128[jj];
            asm("fma.rn.f32x2 %0, %1, %2, %0;"
                : "+l"(a[(2 * jj) & 3]) : "l"(hv.x), "l"(r2[2 * jj]));
            asm("fma.rn.f32x2 %0, %1, %2, %0;"
                : "+l"(a[(2 * jj + 1) & 3]) : "l"(hv.y), "l"(r2[2 * jj + 1]));
        }
        float l0, h0, l1, h1, l2, h2, l3, h3;
        asm("mov.b64 {%0, %1}, %2;" : "=f"(l0), "=f"(h0) : "l"(a[0]));
        asm("mov.b64 {%0, %1}, %2;" : "=f"(l1), "=f"(h1) : "l"(a[1]));
        asm("mov.b64 {%0, %1}, %2;" : "=f"(l2), "=f"(h2) : "l"(a[2]));
        asm("mov.b64 {%0, %1}, %2;" : "=f"(l3), "=f"(h3) : "l"(a[3]));
        float rec = ((l0 + h0) + (l1 + h1)) + ((l2 + h2) + (l3 + h3));

        // Own pre-activation is local: apply per-gate nonlinearity in parallel
        // across all 192 threads BEFORE the sync (tanh/sigmoid off critical path).
        float pre = rec + gbuf0 + cbias;
        float sv;
        if (g == 2)      sv = tanhf(pre);
        else if (g == 3) sv = __fdividef(1.f, 1.f + __expf(-pre));
        else             sv = pre;
        spre[tid] = sv;
        __syncthreads();   // A: spre ready; all hbuf[t&1] reads complete

        if (tid < 48) {
            float i_ = spre[tid];
            float f_ = spre[48 + tid];
            float tz = spre[96 + tid];
            float so = spre[144 + tid];
            float mn = fmaxf(f_ + m, i_);
            float ia = __expf(i_ - mn);
            float fa = __expf(f_ + m - mn);
            c = fa * c + ia * tz;
            n = fa * n + ia;
            m = mn;
            float hn = __fdividef(c, n) * so;

            Yp[(size_t)t * D_] = hn;

            if (t < S_ - 1) {
                // Broadcast h_new[e] into hbuf[(t+1)&1] of all 4 cluster CTAs.
                uint32_t off = (uint32_t)((((t + 1) & 1) * DH_ + q * 48 + tid) * 4);
#pragma unroll
                for (int rk = 0; rk < 4; rk++) {
                    asm volatile("st.shared::cluster.f32 [%0], %1;"
                                 :: "r"(rhb[rk] + off), "f"(hn) : "memory");
                }
            }
        }
        __syncthreads();   // B: h stores issued by gate threads, ordered for release

        // Exactly 4 arrivals per barrier per step: thread rk -> rank rk.
        if (tid < 4 && t < S_ - 1) {
            asm volatile("mbarrier.arrive.release.cluster.shared::cluster.b64 _, [%0];"
                         :: "r"(rmb[tid]) : "memory");
        }

        gbuf0 = gbuf1;
        gbuf1 = gnn;
    }
}

// ---------------------------------------------------------------------------
// Kernel 4: multi-head layernorm over DH per (b,s,h) row.
// ---------------------------------------------------------------------------
__global__ __launch_bounds__(192) void mh_layernorm_kernel(
    const float* __restrict__ gn_scale, float* __restrict__ out)
{
    const int h  = blockIdx.x & (NH_ - 1);
    const int bs = blockIdx.x >> 2;
    const int base = bs * D_ + h * DH_;
    const int tid = threadIdx.x;

    float v = g_yraw[base + tid];
    float s1 = v, s2 = v * v;
#pragma unroll
    for (int o = 16; o; o >>= 1) {
        s1 += __shfl_xor_sync(0xFFFFFFFFu, s1, o);
        s2 += __shfl_xor_sync(0xFFFFFFFFu, s2, o);
    }
    __shared__ float r1[6], r2s[6];
    int w = tid >> 5;
    if ((tid & 31) == 0) { r1[w] = s1; r2s[w] = s2; }
    __syncthreads();
    float t1 = 0.f, t2 = 0.f;
#pragma unroll
    for (int i = 0; i < 6; i++) { t1 += r1[i]; t2 += r2s[i]; }
    const float inv = 1.f / (float)DH_;
    float mu  = t1 * inv;
    float var = t2 * inv - mu * mu;
    float rs  = rsqrtf(var + EPS_);
    out[base + tid] = (v - mu) * rs * gn_scale[h * DH_ + tid];
}

// ---------------------------------------------------------------------------
// Launch
// ---------------------------------------------------------------------------
extern "C" void kernel_launch(void* const* d_in, const int* in_sizes, int n_in,
                              void* d_out, int out_size)
{
    const float* x    = (const float*)d_in[0];
    const float* ck   = (const float*)d_in[1];
    const float* cb   = (const float*)d_in[2];
    const float* Wi   = (const float*)d_in[3];
    const float* Wf   = (const float*)d_in[4];
    const float* Wz   = (const float*)d_in[5];
    const float* Wo   = (const float*)d_in[6];
    const float* R    = (const float*)d_in[7];
    const float* cbi  = (const float*)d_in[8];
    const float* gns  = (const float*)d_in[9];
    float* out = (float*)d_out;

    conv_swish_kernel<<<(B_ * S_ * D_ + 255) / 256, 256>>>(x, ck, cb);
    gate_gemm_kernel<<<dim3(DH_ / 64, (B_ * S_) / 64, 16), 256>>>(x, Wi, Wf, Wz, Wo);
    slstm_scan_kernel<<<64, 192>>>(R, cbi);
    mh_layernorm_kernel<<<B_ * S_ * NH_, 192>>>(gns, out);
}

// round 9
// speedup vs baseline: 1.6233x; 1.6233x over previous
#include <cuda_runtime.h>
#include <cstdint>

// Problem constants
#define B_   4
#define S_   2048
#define D_   768
#define NH_  4
#define DH_  192
#define KC_  4
#define EPS_ 1e-5f

// Scratch (device globals; no allocation allowed)
__device__ float g_xconv[B_ * S_ * D_];            // 25 MB
__device__ float g_G[4 * B_ * S_ * D_];            // 100 MB
__device__ float g_yraw[B_ * S_ * D_];             // 25 MB

// ---------------------------------------------------------------------------
// Kernel 1: causal depthwise conv1d + swish
// ---------------------------------------------------------------------------
__global__ __launch_bounds__(256) void conv_swish_kernel(
    const float* __restrict__ x, const float* __restrict__ ck,
    const float* __restrict__ cb)
{
    int idx = blockIdx.x * 256 + threadIdx.x;
    if (idx >= B_ * S_ * D_) return;
    int d = idx % D_;
    int s = (idx / D_) & (S_ - 1);
    float acc = cb[d];
    const float* xp = x + idx;
#pragma unroll
    for (int j = 0; j < KC_; j++) {
        int ss = s - (KC_ - 1) + j;
        if (ss >= 0) acc += ck[j * D_ + d] * xp[(j - (KC_ - 1)) * D_];
    }
    g_xconv[idx] = acc / (1.f + __expf(-acc));
}

// ---------------------------------------------------------------------------
// Kernel 2: headwise gate GEMMs (R3 version — known good).
// ---------------------------------------------------------------------------
__global__ __launch_bounds__(256) void gate_gemm_kernel(
    const float* __restrict__ x,
    const float* __restrict__ Wi, const float* __restrict__ Wf,
    const float* __restrict__ Wz, const float* __restrict__ Wo)
{
    const int gz = blockIdx.z;
    const int g = gz >> 2;
    const int h = gz & 3;
    const float* A = (g < 2) ? g_xconv : x;
    const float* W = (g == 0) ? Wi : (g == 1) ? Wf : (g == 2) ? Wz : Wo;
    W += (size_t)h * DH_ * DH_;

    const int n0 = blockIdx.x * 64;
    const int m0 = blockIdx.y * 64;

    __shared__ __align__(16) float As[16][68];  // [k][m]
    __shared__ __align__(16) float Bs[16][68];  // [k][e]

    const int tid = threadIdx.x;
    const int tn = tid & 15;
    const int tm = tid >> 4;

    float acc[4][4] = {};

    for (int k0 = 0; k0 < DH_; k0 += 16) {
#pragma unroll
        for (int i = 0; i < 4; i++) {
            int lin = tid + i * 256;
            int r = lin >> 4, cc = lin & 15;
            As[cc][r] = A[(size_t)(m0 + r) * D_ + h * DH_ + k0 + cc];
        }
#pragma unroll
        for (int i = 0; i < 4; i++) {
            int lin = tid + i * 256;
            int r = lin >> 6, cc = lin & 63;
            Bs[r][cc] = W[(size_t)(k0 + r) * DH_ + n0 + cc];
        }
        __syncthreads();
#pragma unroll
        for (int kk = 0; kk < 16; kk++) {
            float4 av = *(const float4*)&As[kk][tm * 4];
            float4 bv = *(const float4*)&Bs[kk][tn * 4];
            acc[0][0] += av.x * bv.x; acc[0][1] += av.x * bv.y;
            acc[0][2] += av.x * bv.z; acc[0][3] += av.x * bv.w;
            acc[1][0] += av.y * bv.x; acc[1][1] += av.y * bv.y;
            acc[1][2] += av.y * bv.z; acc[1][3] += av.y * bv.w;
            acc[2][0] += av.z * bv.x; acc[2][1] += av.z * bv.y;
            acc[2][2] += av.z * bv.z; acc[2][3] += av.z * bv.w;
            acc[3][0] += av.w * bv.x; acc[3][1] += av.w * bv.y;
            acc[3][2] += av.w * bv.z; acc[3][3] += av.w * bv.w;
        }
        __syncthreads();
    }

#pragma unroll
    for (int i = 0; i < 4; i++) {
        int mm = m0 + tm * 4 + i;
        int bb = mm >> 11;
        int ss = mm & (S_ - 1);
        float4 v = make_float4(acc[i][0], acc[i][1], acc[i][2], acc[i][3]);
        *(float4*)&g_G[((size_t)(bb * NH_ + h) * S_ + ss) * D_ + g * DH_ + n0 + tn * 4] = v;
    }
}

// ---------------------------------------------------------------------------
// Kernel 3: sequential sLSTM scan — st.async transaction protocol.
// One cluster of 4 CTAs per (b,h) chain; CTA rank q owns e in [48q, 48q+48).
// 192 threads: thread t handles gate g=t/48, local column el=t%48.
// R slice in registers as 96 f32x2 pairs.
//
// Sync: one mbarrier per CTA, init count=1. Per step (phase p = t):
//   tid0 arms arrive.expect_tx(768B) after entering the phase;
//   gate threads publish h via st.async.shared::cluster with
//   mbarrier::complete_tx::bytes (4B tx each, 4 ranks x 48 threads x 4B = 768B);
//   consumers try_wait.parity.acquire.cluster at the next step.
// Signal rides with the data: no cluster.sync (no per-step L1D flush), no
// separate arrive hop, no second __syncthreads.
// WAR safety: remote overwrites of hbuf[t&1] (phase t+1 stores) require the
// remote to pass wait(phase t), which needs OUR phase-t stores, issued after
// our __syncthreads A, i.e. after all our hbuf[t&1] reads.
// ---------------------------------------------------------------------------
__device__ __forceinline__ uint32_t smem_u32(const void* p) {
    uint32_t a;
    asm("{ .reg .u64 t; cvta.to.shared.u64 t, %1; cvt.u32.u64 %0, t; }"
        : "=r"(a) : "l"(p));
    return a;
}

#define CLUSTER_SYNC_() do { \
    asm volatile("barrier.cluster.arrive.aligned;" ::: "memory"); \
    asm volatile("barrier.cluster.wait.aligned;"   ::: "memory"); \
} while (0)

__device__ __forceinline__ void mbar_wait_acq(uint32_t addr, uint32_t parity) {
    uint32_t done;
    asm volatile("{\n\t.reg .pred p;\n\t"
        "mbarrier.try_wait.parity.acquire.cluster.shared::cta.b64 p, [%1], %2;\n\t"
        "selp.b32 %0, 1, 0, p;\n\t}"
        : "=r"(done) : "r"(addr), "r"(parity) : "memory");
    if (!done) {
        asm volatile("{\n\t.reg .pred P1;\n\t"
            "WL_%=:\n\t"
            "mbarrier.try_wait.parity.acquire.cluster.shared::cta.b64 P1, [%0], %1, 0x989680;\n\t"
            "@P1 bra.uni WD_%=;\n\t"
            "bra.uni WL_%=;\n\t"
            "WD_%=:\n\t}"
            :: "r"(addr), "r"(parity) : "memory");
    }
}

#define TX_BYTES_ (DH_ * 4)   // 768: full h per phase

__global__ void __cluster_dims__(4, 1, 1) __launch_bounds__(192, 1)
slstm_scan_kernel(const float* __restrict__ R, const float* __restrict__ cell_bias)
{
    __shared__ __align__(16) float hbuf[2][DH_];
    __shared__ float spre[4 * 48];     // i, f, tanh(z), sigmoid(o)
    __shared__ __align__(8) unsigned long long mbar;

    const int tid   = threadIdx.x;
    const int chain = blockIdx.x >> 2;      // 0..15
    const int q     = blockIdx.x & 3;       // cluster rank
    const int b     = chain >> 2;
    const int h     = chain & 3;
    const int g     = tid / 48;
    const int el    = tid % 48;
    const int e     = q * 48 + el;

    // Load this thread's R column as 96 packed f32x2 pairs (over d).
    unsigned long long r2[96];
    {
        const float* Rcol = R + ((size_t)(g * NH_ + h)) * DH_ * DH_ + e;
#pragma unroll
        for (int j = 0; j < 96; j++) {
            float lo = Rcol[(2 * j) * DH_];
            float hi = Rcol[(2 * j + 1) * DH_];
            asm("mov.b64 %0, {%1, %2};" : "=l"(r2[j]) : "f"(lo), "f"(hi));
        }
    }
    const float cbias = cell_bias[g * D_ + h * DH_ + e];

    const float* Gp = g_G + ((size_t)(b * NH_ + h)) * S_ * D_ + g * DH_ + e;
    float* Yp = g_yraw + (size_t)b * S_ * D_ + h * DH_ + e;

    const uint32_t hb_base = smem_u32(&hbuf[0][0]);
    const uint32_t mb_addr = smem_u32(&mbar);

    hbuf[0][tid] = 0.f;
    hbuf[1][tid] = 0.f;
    if (tid == 0) {
        asm volatile("mbarrier.init.shared.b64 [%0], %1;"
                     :: "r"(mb_addr), "r"(1) : "memory");
        // Arm phase 0 before anyone can send (pre-cluster.sync).
        asm volatile("mbarrier.arrive.expect_tx.shared.b64 _, [%0], %1;"
                     :: "r"(mb_addr), "r"(TX_BYTES_) : "memory");
    }
    __syncthreads();
    CLUSTER_SYNC_();   // hbuf + armed mbarrier visible cluster-wide (once)

    // Remote hbuf and mbarrier addresses for all 4 ranks.
    uint32_t rhb[4], rmb[4];
#pragma unroll
    for (int rk = 0; rk < 4; rk++) {
        asm("mapa.shared::cluster.u32 %0, %1, %2;" : "=r"(rhb[rk]) : "r"(hb_base), "r"(rk));
        asm("mapa.shared::cluster.u32 %0, %1, %2;" : "=r"(rmb[rk]) : "r"(mb_addr), "r"(rk));
    }

    float c = 0.f, n = 0.f, m = 0.f;

    // 2-deep G prefetch ring.
    float gbuf0 = Gp[0];
    float gbuf1 = Gp[D_];

    for (int t = 0; t < S_; ++t) {
        float gnn = (t + 2 < S_) ? Gp[(size_t)(t + 2) * D_] : 0.f;

        if (t > 0) {
            // Wait for phase t-1 (all 768B of h(t) delivered).
            mbar_wait_acq(mb_addr, (uint32_t)((t - 1) & 1));
            // Arm phase t (single arrival; tx may already be partially/fully
            // delivered by fast ranks — negative pending tx is fine since the
            // phase needs this arrival to complete).
            if (tid == 0 && t <= S_ - 2) {
                asm volatile("mbarrier.arrive.expect_tx.shared.b64 _, [%0], %1;"
                             :: "r"(mb_addr), "r"(TX_BYTES_) : "memory");
            }
        }

        // Recurrent matvec: rec[e] = sum_d h[d] * R[g][h][d][e]
        const ulonglong2* h128 = (const ulonglong2*)hbuf[t & 1];
        unsigned long long a[4] = {0ull, 0ull, 0ull, 0ull};
#pragma unroll
        for (int jj = 0; jj < 48; jj++) {
            ulonglong2 hv = h128[jj];
            asm("fma.rn.f32x2 %0, %1, %2, %0;"
                : "+l"(a[(2 * jj) & 3]) : "l"(hv.x), "l"(r2[2 * jj]));
            asm("fma.rn.f32x2 %0, %1, %2, %0;"
                : "+l"(a[(2 * jj + 1) & 3]) : "l"(hv.y), "l"(r2[2 * jj + 1]));
        }
        float l0, h0, l1, h1, l2, h2, l3, h3;
        asm("mov.b64 {%0, %1}, %2;" : "=f"(l0), "=f"(h0) : "l"(a[0]));
        asm("mov.b64 {%0, %1}, %2;" : "=f"(l1), "=f"(h1) : "l"(a[1]));
        asm("mov.b64 {%0, %1}, %2;" : "=f"(l2), "=f"(h2) : "l"(a[2]));
        asm("mov.b64 {%0, %1}, %2;" : "=f"(l3), "=f"(h3) : "l"(a[3]));
        float rec = ((l0 + h0) + (l1 + h1)) + ((l2 + h2) + (l3 + h3));

        // Per-gate nonlinearity in parallel BEFORE the sync.
        float pre = rec + gbuf0 + cbias;
        float sv;
        if (g == 2)      sv = tanhf(pre);
        else if (g == 3) sv = __fdividef(1.f, 1.f + __expf(-pre));
        else             sv = pre;
        spre[tid] = sv;
        __syncthreads();   // A: spre ready; all hbuf[t&1] reads complete

        if (tid < 48) {
            float i_ = spre[tid];
            float f_ = spre[48 + tid];
            float tz = spre[96 + tid];
            float so = spre[144 + tid];
            float mn = fmaxf(f_ + m, i_);
            float ia = __expf(i_ - mn);
            float fa = __expf(f_ + m - mn);
            c = fa * c + ia * tz;
            n = fa * n + ia;
            m = mn;
            float hn = __fdividef(c, n) * so;

            Yp[(size_t)t * D_] = hn;

            if (t < S_ - 1) {
                // Publish h_new[e] to hbuf[(t+1)&1] of all 4 ranks; each store
                // carries 4B of transaction to that rank's mbarrier.
                uint32_t off = (uint32_t)((((t + 1) & 1) * DH_ + q * 48 + tid) * 4);
                uint32_t hv; asm("mov.b32 %0, %1;" : "=r"(hv) : "f"(hn));
#pragma unroll
                for (int rk = 0; rk < 4; rk++) {
                    asm volatile(
                        "st.async.shared::cluster.mbarrier::complete_tx::bytes.b32 [%0], %1, [%2];"
                        :: "r"(rhb[rk] + off), "r"(hv), "r"(rmb[rk]) : "memory");
                }
            }
        }

        gbuf0 = gbuf1;
        gbuf1 = gnn;
    }

    CLUSTER_SYNC_();   // no CTA exits while peers might still address its smem
}

// ---------------------------------------------------------------------------
// Kernel 4: multi-head layernorm over DH per (b,s,h) row.
// ---------------------------------------------------------------------------
__global__ __launch_bounds__(192) void mh_layernorm_kernel(
    const float* __restrict__ gn_scale, float* __restrict__ out)
{
    const int h  = blockIdx.x & (NH_ - 1);
    const int bs = blockIdx.x >> 2;
    const int base = bs * D_ + h * DH_;
    const int tid = threadIdx.x;

    float v = g_yraw[base + tid];
    float s1 = v, s2 = v * v;
#pragma unroll
    for (int o = 16; o; o >>= 1) {
        s1 += __shfl_xor_sync(0xFFFFFFFFu, s1, o);
        s2 += __shfl_xor_sync(0xFFFFFFFFu, s2, o);
    }
    __shared__ float r1[6], r2s[6];
    int w = tid >> 5;
    if ((tid & 31) == 0) { r1[w] = s1; r2s[w] = s2; }
    __syncthreads();
    float t1 = 0.f, t2 = 0.f;
#pragma unroll
    for (int i = 0; i < 6; i++) { t1 += r1[i]; t2 += r2s[i]; }
    const float inv = 1.f / (float)DH_;
    float mu  = t1 * inv;
    float var = t2 * inv - mu * mu;
    float rs  = rsqrtf(var + EPS_);
    out[base + tid] = (v - mu) * rs * gn_scale[h * DH_ + tid];
}

// ---------------------------------------------------------------------------
// Launch
// ---------------------------------------------------------------------------
extern "C" void kernel_launch(void* const* d_in, const int* in_sizes, int n_in,
                              void* d_out, int out_size)
{
    const float* x    = (const float*)d_in[0];
    const float* ck   = (const float*)d_in[1];
    const float* cb   = (const float*)d_in[2];
    const float* Wi   = (const float*)d_in[3];
    const float* Wf   = (const float*)d_in[4];
    const float* Wz   = (const float*)d_in[5];
    const float* Wo   = (const float*)d_in[6];
    const float* R    = (const float*)d_in[7];
    const float* cbi  = (const float*)d_in[8];
    const float* gns  = (const float*)d_in[9];
    float* out = (float*)d_out;

    conv_swish_kernel<<<(B_ * S_ * D_ + 255) / 256, 256>>>(x, ck, cb);
    gate_gemm_kernel<<<dim3(DH_ / 64, (B_ * S_) / 64, 16), 256>>>(x, Wi, Wf, Wz, Wo);
    slstm_scan_kernel<<<64, 192>>>(R, cbi);
    mh_layernorm_kernel<<<B_ * S_ * NH_, 192>>>(gns, out);
}